// round 16
// baseline (speedup 1.0000x reference)
#include <cuda_runtime.h>
#include <math.h>

#define BATCH 512
#define NGEN 4095
#define THETA_STRIDE 4096
#define HID 256
#define INDIM 768
#define CHUNK 512
#define NOBS 15

typedef unsigned long long ull;

// ---------------- f32x2 packed helpers (Blackwell) ----------------
__device__ __forceinline__ ull pk2(float lo, float hi) {
    ull r; asm("mov.b64 %0, {%1, %2};" : "=l"(r) : "f"(lo), "f"(hi)); return r;
}
__device__ __forceinline__ void upk2(ull v, float& lo, float& hi) {
    asm("mov.b64 {%0, %1}, %2;" : "=f"(lo), "=f"(hi) : "l"(v));
}
__device__ __forceinline__ ull fma2(ull a, ull b, ull c) {
    ull d; asm("fma.rn.f32x2 %0, %1, %2, %3;" : "=l"(d) : "l"(a), "l"(b), "l"(c)); return d;
}

// ---------------- scratch ----------------
__device__ float g_hid[BATCH * HID];
__device__ float g_theta[BATCH * THETA_STRIDE];
__device__ float g_hid2[BATCH * HID];

// ---------------- unified GEMM: 64x64 tile, BK=16, double-buffered prefetch ----------------
// Exact in M and K (64|M, 16|K, aligned A rows). EDGE=true allows ragged N
// (scalar guarded B loads + guarded C stores; needed when 4 !| N too, for alignment).
#define SA_S 132   // padded A row stride (words)
#define SB_S 68    // padded B row stride
template <bool SILU, bool EDGE>
__global__ __launch_bounds__(256) void gemm64_kernel(
    const float* __restrict__ A, const float* __restrict__ B,
    const float* __restrict__ bias, float* __restrict__ C,
    int M, int N, int K, int lda, int ldc)
{
    __shared__ __align__(16) float As2[2][16][SA_S];   // duplicated (a,a) pairs
    __shared__ __align__(16) float Bs[2][16][SB_S];
    const int tid = threadIdx.x;
    const int tx = tid % 16, ty = tid / 16;
    const int brow = blockIdx.y * 64, bcol = blockIdx.x * 64;

    const int ar = tid >> 2, ac4 = (tid & 3) * 4;      // A: float4 at (row ar, cols ac4..+3)
    const int br = tid >> 4, bc4 = (tid & 15) * 4;     // B: 4 floats at (row br, cols bc4..+3)

    ull acc[4][2];
#pragma unroll
    for (int i = 0; i < 4; ++i) { acc[i][0] = 0ull; acc[i][1] = 0ull; }

    const int nk = K >> 4;

    float4 a_st = *reinterpret_cast<const float4*>(&A[(brow + ar) * lda + ac4]);
    float4 b_st;
    if (!EDGE) {
        b_st = *reinterpret_cast<const float4*>(&B[br * N + bcol + bc4]);
    } else {
        const float* bp = &B[br * N + bcol + bc4];
        int gc = bcol + bc4;
        b_st.x = (gc + 0 < N) ? bp[0] : 0.f;
        b_st.y = (gc + 1 < N) ? bp[1] : 0.f;
        b_st.z = (gc + 2 < N) ? bp[2] : 0.f;
        b_st.w = (gc + 3 < N) ? bp[3] : 0.f;
    }

    // store tile 0
    {
        float2* p0 = reinterpret_cast<float2*>(&As2[0][ac4][2 * ar]);
        float2* p1 = reinterpret_cast<float2*>(&As2[0][ac4 + 1][2 * ar]);
        float2* p2 = reinterpret_cast<float2*>(&As2[0][ac4 + 2][2 * ar]);
        float2* p3 = reinterpret_cast<float2*>(&As2[0][ac4 + 3][2 * ar]);
        *p0 = make_float2(a_st.x, a_st.x);
        *p1 = make_float2(a_st.y, a_st.y);
        *p2 = make_float2(a_st.z, a_st.z);
        *p3 = make_float2(a_st.w, a_st.w);
        *reinterpret_cast<float4*>(&Bs[0][br][bc4]) = b_st;
    }
    __syncthreads();

    for (int kb = 0; kb < nk; ++kb) {
        int cur = kb & 1;
        if (kb + 1 < nk) {
            int k0 = (kb + 1) * 16;
            a_st = *reinterpret_cast<const float4*>(&A[(brow + ar) * lda + k0 + ac4]);
            if (!EDGE) {
                b_st = *reinterpret_cast<const float4*>(&B[(k0 + br) * N + bcol + bc4]);
            } else {
                const float* bp = &B[(k0 + br) * N + bcol + bc4];
                int gc = bcol + bc4;
                b_st.x = (gc + 0 < N) ? bp[0] : 0.f;
                b_st.y = (gc + 1 < N) ? bp[1] : 0.f;
                b_st.z = (gc + 2 < N) ? bp[2] : 0.f;
                b_st.w = (gc + 3 < N) ? bp[3] : 0.f;
            }
        }
#pragma unroll
        for (int kk = 0; kk < 16; ++kk) {
            ulonglong2 aA = *reinterpret_cast<const ulonglong2*>(&As2[cur][kk][ty * 8]);
            ulonglong2 aB = *reinterpret_cast<const ulonglong2*>(&As2[cur][kk][ty * 8 + 4]);
            ulonglong2 bb = *reinterpret_cast<const ulonglong2*>(&Bs[cur][kk][tx * 4]);
            acc[0][0] = fma2(aA.x, bb.x, acc[0][0]); acc[0][1] = fma2(aA.x, bb.y, acc[0][1]);
            acc[1][0] = fma2(aA.y, bb.x, acc[1][0]); acc[1][1] = fma2(aA.y, bb.y, acc[1][1]);
            acc[2][0] = fma2(aB.x, bb.x, acc[2][0]); acc[2][1] = fma2(aB.x, bb.y, acc[2][1]);
            acc[3][0] = fma2(aB.y, bb.x, acc[3][0]); acc[3][1] = fma2(aB.y, bb.y, acc[3][1]);
        }
        if (kb + 1 < nk) {
            int nxt = (kb + 1) & 1;
            float2* p0 = reinterpret_cast<float2*>(&As2[nxt][ac4][2 * ar]);
            float2* p1 = reinterpret_cast<float2*>(&As2[nxt][ac4 + 1][2 * ar]);
            float2* p2 = reinterpret_cast<float2*>(&As2[nxt][ac4 + 2][2 * ar]);
            float2* p3 = reinterpret_cast<float2*>(&As2[nxt][ac4 + 3][2 * ar]);
            *p0 = make_float2(a_st.x, a_st.x);
            *p1 = make_float2(a_st.y, a_st.y);
            *p2 = make_float2(a_st.z, a_st.z);
            *p3 = make_float2(a_st.w, a_st.w);
            *reinterpret_cast<float4*>(&Bs[nxt][br][bc4]) = b_st;
        }
        __syncthreads();
    }

#pragma unroll
    for (int i = 0; i < 4; ++i) {
        int row = brow + ty * 4 + i;
#pragma unroll
        for (int p = 0; p < 2; ++p) {
            float c0, c1;
            upk2(acc[i][p], c0, c1);
            int col0 = bcol + tx * 4 + 2 * p;
            if (!EDGE || col0 < N) {
                float v0 = c0 + bias[col0];
                if (SILU) v0 = v0 / (1.f + expf(-v0));
                C[row * ldc + col0] = v0;
            }
            if (!EDGE || col0 + 1 < N) {
                float v1 = c1 + bias[col0 + 1];
                if (SILU) v1 = v1 / (1.f + expf(-v1));
                C[row * ldc + col0 + 1] = v1;
            }
        }
    }
}

__global__ void dummy_kernel() {}

// ---------------- quantum kernel v5: RMT lambda, broadcast matvec ----------------
__device__ __forceinline__ int spread6(int v) {
    return (v & 1) | ((v & 2) << 1) | ((v & 4) << 2) | ((v & 8) << 3) |
           ((v & 16) << 4) | ((v & 32) << 5);
}

__device__ __forceinline__ void pauli_coef_raw(int x, int z, const float* __restrict__ th,
                                               float& cr, float& ci)
{
    if ((x | z) == 0) { cr = 0.f; ci = 0.f; return; }
    int idx4 = spread6(x ^ z) | (spread6(z) << 1);
    float v = __ldg(th + idx4 - 1);
    int p = __popc(x & z) & 3;               // (-i)^p
    cr = (p == 0) ? v : ((p == 2) ? -v : 0.f);
    ci = (p == 1) ? -v : ((p == 3) ? v : 0.f);
}

#define PHASEA() do {                                                              \
    const float4* _vp = reinterpret_cast<const float4*>(&vv[buf][slice * 8]);      \
    float4 _a0 = _vp[0], _a1 = _vp[1];                                             \
    float _pr0, _pi0, _pr1, _pi1;                                                  \
    _pr0 = hr[0] * _a0.x - hi[0] * _a0.y;  _pi0 = hr[0] * _a0.y + hi[0] * _a0.x;   \
    _pr1 = hr[1] * _a0.z - hi[1] * _a0.w;  _pi1 = hr[1] * _a0.w + hi[1] * _a0.z;   \
    _pr0 += hr[2] * _a1.x - hi[2] * _a1.y; _pi0 += hr[2] * _a1.y + hi[2] * _a1.x;  \
    _pr1 += hr[3] * _a1.z - hi[3] * _a1.w; _pi1 += hr[3] * _a1.w + hi[3] * _a1.z;  \
    float4 _a2 = _vp[2], _a3 = _vp[3];                                             \
    _pr0 += hr[4] * _a2.x - hi[4] * _a2.y; _pi0 += hr[4] * _a2.y + hi[4] * _a2.x;  \
    _pr1 += hr[5] * _a2.z - hi[5] * _a2.w; _pi1 += hr[5] * _a2.w + hi[5] * _a2.z;  \
    _pr0 += hr[6] * _a3.x - hi[6] * _a3.y; _pi0 += hr[6] * _a3.y + hi[6] * _a3.x;  \
    _pr1 += hr[7] * _a3.z - hi[7] * _a3.w; _pi1 += hr[7] * _a3.w + hi[7] * _a3.z;  \
    spart[slice * 64 + row] = make_float2(_pr0 + _pr1, _pi0 + _pi1);               \
} while (0)

__global__ __launch_bounds__(512, 3) void quantum_kernel(
    const float* __restrict__ theta_all,
    const float* __restrict__ Aoff, const float* __restrict__ Boff,
    const float* __restrict__ Ddiag,
    const float* __restrict__ Wv1, const float* __restrict__ bv1,
    float* __restrict__ hid2_out)
{
    const int b = blockIdx.x;
    const float* th = theta_all + b * THETA_STRIDE;
    const int t = threadIdx.x;
    const int lane = t & 31, warp = t >> 5;

    __shared__ float sHr[64 * 65];
    __shared__ float sHi[64 * 65];
    __shared__ __align__(16) float2 vv[2][64];
    __shared__ __align__(16) float2 spart[512];
    __shared__ float spr[64], spi[64];
    __shared__ float sJ[128];
    __shared__ float s_sin[128];
    __shared__ float sred[16];
    __shared__ float s_scl[4];
    __shared__ float sq[16];
    __shared__ int s_K;

    // --- sum theta^2 -> lambda_F ---
    float ss = 0.f;
    for (int m = t; m < NGEN; m += 512) { float v = __ldg(th + m); ss += v * v; }
#pragma unroll
    for (int d = 16; d; d >>= 1) ss += __shfl_xor_sync(0xffffffffu, ss, d);
    if (lane == 0) sred[warp] = ss;

    // --- quadrature sin table (128-pt) ---
    if (t < 128) s_sin[t] = __sinf((float)t * 0.049087385212f);  // 2*pi/128

    // --- build raw H via 64-pt WHT per x-mask (16 warps -> 4 passes) ---
    for (int pass = 0; pass < 4; ++pass) {
        int x = pass * 16 + warp;
        float ar, ai, br, bi;
        pauli_coef_raw(x, lane, th, ar, ai);
        pauli_coef_raw(x, lane + 32, th, br, bi);
        float t0r = ar + br, t0i = ai + bi;
        float t1r = ar - br, t1i = ai - bi;
#pragma unroll
        for (int d = 16; d >= 1; d >>= 1) {
            float o;
            o = __shfl_xor_sync(0xffffffffu, t0r, d); t0r = (lane & d) ? (o - t0r) : (t0r + o);
            o = __shfl_xor_sync(0xffffffffu, t0i, d); t0i = (lane & d) ? (o - t0i) : (t0i + o);
            o = __shfl_xor_sync(0xffffffffu, t1r, d); t1r = (lane & d) ? (o - t1r) : (t1r + o);
            o = __shfl_xor_sync(0xffffffffu, t1i, d); t1i = (lane & d) ? (o - t1i) : (t1i + o);
        }
        sHr[lane * 65 + (lane ^ x)] = t0r;
        sHi[lane * 65 + (lane ^ x)] = t0i;
        int r2 = lane + 32;
        sHr[r2 * 65 + (r2 ^ x)] = t1r;
        sHi[r2 * 65 + (r2 ^ x)] = t1i;
    }
    __syncthreads();

    // --- stage H slice: row = t&63, slice = t>>6 ---
    const int row = t & 63, slice = t >> 6, cb = slice * 8;
    float hr[8], hi[8];
#pragma unroll
    for (int j = 0; j < 8; ++j) {
        hr[j] = sHr[row * 65 + cb + j];
        hi[j] = sHi[row * 65 + cb + j];
    }

    // --- RMT lambda + K (thread 0), e0 init ---
    if (t == 0) {
        float tot = 0.f;
#pragma unroll
        for (int i = 0; i < 16; ++i) tot += sred[i];
        float lamF = sqrtf(64.f * fmaxf(tot, 1e-12f));
        float lu = fmaxf(0.285f * lamF, 1e-3f);
        int K = (int)ceilf(lu + 3.0f * cbrtf(lu) + 2.f);
        if (K < 6) K = 6;
        if (K > 99) K = 99;
        s_scl[0] = lu;
        s_scl[1] = 1.f / lu;
        s_K = K;
    }
    if (t < 64) vv[0][t] = make_float2((t == 0) ? 1.f : 0.f, 0.f);
    __syncthreads();
    const float invl = s_scl[1];
    const int K = s_K;

    // --- Bessel J_k via 128-pt DFT quadrature ---
    if (t < 128) s_sin[t] *= s_scl[0];
    __syncthreads();
    {
        int k = t >> 2, jb = t & 3;
        const float C0 = 0.049087385212f;  // 2*pi/128
        int idx = (k * jb) & 127;
        int step = (4 * k) & 127;
        float sum = 0.f;
        int j = jb;
#pragma unroll 8
        for (int i = 0; i < 32; ++i) {
            float ang = fmaf((float)idx, C0, -s_sin[j]);
            sum += __cosf(ang);
            idx = (idx + step) & 127;
            j += 4;
        }
        sum += __shfl_xor_sync(0xffffffffu, sum, 1);
        sum += __shfl_xor_sync(0xffffffffu, sum, 2);
        if (jb == 0) sJ[k] = sum * (1.f / 128.f);
    }
    __syncthreads();

    // --- Chebyshev: psi = sum c_k T_k(H/lu) e0 ---
    int buf = 0;
    float cur_r = 0.f, cur_i = 0.f, prev_r = 0.f, prev_i = 0.f;
    float psi_r = 0.f, psi_i = 0.f;
    if (t < 64) {
        cur_r = (t == 0) ? 1.f : 0.f;
        psi_r = sJ[0] * cur_r;
    }

    for (int k = 1; k <= K; ++k) {
        PHASEA();
        __syncthreads();
        if (t < 64) {
            float ar = 0.f, ai = 0.f;
#pragma unroll
            for (int s = 0; s < 8; ++s) {
                float2 p = spart[s * 64 + t];
                ar += p.x; ai += p.y;
            }
            ar *= invl; ai *= invl;
            float tnr, tni;
            if (k == 1) { tnr = ar; tni = ai; }
            else        { tnr = 2.f * ar - prev_r; tni = 2.f * ai - prev_i; }
            float cj = 2.f * sJ[k];
            switch (k & 3) {
                case 0: psi_r += cj * tnr; psi_i += cj * tni; break;
                case 1: psi_r -= cj * tni; psi_i += cj * tnr; break;
                case 2: psi_r -= cj * tnr; psi_i -= cj * tni; break;
                case 3: psi_r += cj * tni; psi_i -= cj * tnr; break;
            }
            prev_r = cur_r; prev_i = cur_i;
            cur_r = tnr;    cur_i = tni;
            vv[buf ^ 1][t] = make_float2(tnr, tni);
        }
        __syncthreads();
        buf ^= 1;
    }
    if (t < 64) { spr[t] = psi_r; spi[t] = psi_i; }

    // --- renormalize |psi> ---
    {
        float n = (t < 64) ? (psi_r * psi_r + psi_i * psi_i) : 0.f;
#pragma unroll
        for (int d = 16; d; d >>= 1) n += __shfl_xor_sync(0xffffffffu, n, d);
        if (lane == 0) sred[warp] = n;
        __syncthreads();
        if (t == 0) {
            float tot = sred[0] + sred[1];
            s_scl[2] = 1.f / fmaxf(tot, 1e-30f);
        }
        __syncthreads();
    }

    // --- 15 two-local observables -> sq ---
    if (t < NOBS) {
        const int wa[15] = {0,0,0,0,0,1,1,1,1,2,2,2,3,3,4};
        const int wb[15] = {1,2,3,4,5,2,3,4,5,3,4,5,4,5,5};
        int a = wa[t], bq = wb[t];
        int pa = 5 - a, pb = 5 - bq;
        float Hd[4];
        Hd[0] = 2.f * __ldg(Ddiag + t * 4 + 1);
        Hd[1] = 2.f * __ldg(Ddiag + t * 4 + 2);
        Hd[2] = 2.f * __ldg(Ddiag + t * 4 + 3);
        Hd[3] = 0.f;
        float Ac[6], Bc[6];
#pragma unroll
        for (int c = 0; c < 6; ++c) {
            Ac[c] = __ldg(Aoff + t * 6 + c);
            Bc[c] = __ldg(Boff + t * 6 + c);
        }
        const int kk_[6] = {1, 2, 2, 3, 3, 3};
        const int ll_[6] = {0, 0, 1, 0, 1, 2};
        float q = 0.f;
        for (int r = 0; r < 16; ++r) {
            int idx0 = 0, rr = r;
#pragma unroll
            for (int p = 0; p < 6; ++p) {
                if (p != pa && p != pb) { idx0 |= (rr & 1) << p; rr >>= 1; }
            }
            float xr[4], xi[4];
#pragma unroll
            for (int k = 0; k < 4; ++k) {
                int idx = idx0 | (((k >> 1) & 1) << pa) | ((k & 1) << pb);
                xr[k] = spr[idx]; xi[k] = spi[idx];
            }
#pragma unroll
            for (int k = 0; k < 4; ++k) q += Hd[k] * (xr[k] * xr[k] + xi[k] * xi[k]);
#pragma unroll
            for (int c = 0; c < 6; ++c) {
                int k = kk_[c], l = ll_[c];
                float rr2 = xr[k] * xr[l] + xi[k] * xi[l];
                float ii2 = xi[k] * xr[l] - xr[k] * xi[l];
                q += 2.f * (Ac[c] * rr2 + Bc[c] * ii2);
            }
        }
        sq[t] = q * s_scl[2];
    }
    __syncthreads();

    // --- fused vel-head layer 1 (first 256 threads) ---
    if (t < HID) {
        float h = __ldg(bv1 + t);
#pragma unroll
        for (int o = 0; o < NOBS; ++o) h = fmaf(sq[o], __ldg(Wv1 + o * HID + t), h);
        h = h / (1.f + expf(-h));
        hid2_out[b * HID + t] = h;
    }
}

// ---------------- launch ----------------
extern "C" void kernel_launch(void* const* d_in, const int* in_sizes, int n_in,
                              void* d_out, int out_size)
{
    const float* x    = (const float*)d_in[0];
    const float* W1   = (const float*)d_in[1];
    const float* b1   = (const float*)d_in[2];
    const float* W2   = (const float*)d_in[3];
    const float* b2   = (const float*)d_in[4];
    const float* Aoff = (const float*)d_in[5];
    const float* Boff = (const float*)d_in[6];
    const float* Dd   = (const float*)d_in[7];
    const float* Wv1  = (const float*)d_in[8];
    const float* bv1  = (const float*)d_in[9];
    const float* Wv2  = (const float*)d_in[10];
    const float* bv2  = (const float*)d_in[11];
    float* out = (float*)d_out;

    float* hid;   cudaGetSymbolAddress((void**)&hid,   g_hid);
    float* theta; cudaGetSymbolAddress((void**)&theta, g_theta);
    float* hid2;  cudaGetSymbolAddress((void**)&hid2,  g_hid2);

    {
        dim3 g(HID / 64, BATCH / 64);
        gemm64_kernel<true, false><<<g, 256>>>(x, W1, b1, hid, BATCH, HID, INDIM, INDIM, HID);
    }
    // two dummies so the NEW big GEMM is my 4th launch (ncu captures it)
    dummy_kernel<<<1, 1>>>();
    dummy_kernel<<<1, 1>>>();
    {
        dim3 g((NGEN + 63) / 64, BATCH / 64);
        gemm64_kernel<false, true><<<g, 256>>>(hid, W2, b2, theta, BATCH, NGEN, HID, HID, THETA_STRIDE);
    }
    quantum_kernel<<<BATCH, 512>>>(theta, Aoff, Boff, Dd, Wv1, bv1, hid2);
    {
        dim3 g(CHUNK / 64, BATCH / 64);
        gemm64_kernel<false, false><<<g, 256>>>(hid2, Wv2, bv2, out, BATCH, CHUNK, HID, HID, CHUNK);
    }
}